// round 1
// baseline (speedup 1.0000x reference)
#include <cuda_runtime.h>
#include <cuda_bf16.h>

// ManifoldConstrainedHyperConnection fused kernel.
//
// Per token n (8192 tokens of shape (W=4, D=2048)):
//   mx[d]   = mean_w x[w,d]
//   raw[k]  = sum_d mx[d] * Wr[k,d] + b[k]          k < 24
//   pre     = softmax(raw[0:4]);  post = softmax(raw[4:8])
//   res     = sinkhorn4(exp(raw[8:24].as(4,4) + (2 on diag, -2 off)))
//   M[i][j] = res[i][j] + post[i]*pre[j]
//   out[i,d]= sum_j M[i][j] * x[j,d]
//
// One CTA per SM (persistent, grid-stride over tokens). W_router lives in
// shared memory (192KB). Each of 512 threads owns a 4-float d-slice.

#define WRK 24          // router rows (W*W + 2W)
#define DDIM 2048
#define WSTREAMS 4
#define THREADS 512
#define PSTRIDE 25      // padded row stride (floats) for partial staging; 25 coprime 32 -> conflict-free
#define PROWS 256       // 16 warps * 16 lanes after the xor-16 fold
#define EPSV 1e-6f

// smem layout (floats): [0, 24*2048) Wr | [.., +256*25) partial stage | raw[32] | M[16]
#define SMEM_WR_FLOATS   (WRK * DDIM)
#define SMEM_P_FLOATS    (PROWS * PSTRIDE)
#define SMEM_FLOATS      (SMEM_WR_FLOATS + SMEM_P_FLOATS + 32 + 16)
#define SMEM_BYTES       (SMEM_FLOATS * 4)

__global__ void __launch_bounds__(THREADS, 1)
mchc_fused_kernel(const float* __restrict__ x,
                  const float* __restrict__ Wr,
                  const float* __restrict__ br,
                  float* __restrict__ out,
                  int ntok)
{
    extern __shared__ float smem[];
    float* sWr  = smem;
    float* sP   = smem + SMEM_WR_FLOATS;
    float* sRaw = sP + SMEM_P_FLOATS;
    float* sM   = sRaw + 32;

    const int tid  = threadIdx.x;
    const int lane = tid & 31;
    const int warp = tid >> 5;
    const unsigned FULL = 0xffffffffu;

    // ---- stage W_router into shared memory (once per CTA) ----
    for (int i = tid * 4; i < SMEM_WR_FLOATS; i += THREADS * 4) {
        float4 v = *reinterpret_cast<const float4*>(Wr + i);
        *reinterpret_cast<float4*>(sWr + i) = v;
    }
    __syncthreads();

    const int d0 = tid * 4;               // this thread's d-slice [d0, d0+4)

    for (int n = blockIdx.x; n < ntok; n += gridDim.x) {
        const float* xt = x + (size_t)n * (WSTREAMS * DDIM);
        float*       ot = out + (size_t)n * (WSTREAMS * DDIM);

        // ---- load x slice for all 4 streams (streaming hint) ----
        float4 xv[WSTREAMS];
        #pragma unroll
        for (int w = 0; w < WSTREAMS; w++)
            xv[w] = __ldcs(reinterpret_cast<const float4*>(xt + w * DDIM + d0));

        // mean over streams
        float4 mx;
        mx.x = (xv[0].x + xv[1].x + xv[2].x + xv[3].x) * 0.25f;
        mx.y = (xv[0].y + xv[1].y + xv[2].y + xv[3].y) * 0.25f;
        mx.z = (xv[0].z + xv[1].z + xv[2].z + xv[3].z) * 0.25f;
        mx.w = (xv[0].w + xv[1].w + xv[2].w + xv[3].w) * 0.25f;

        // ---- router partials: p[k] = mx(slice) . Wr[k](slice) ----
        float p[WRK];
        #pragma unroll
        for (int k = 0; k < WRK; k++) {
            float4 wv = *reinterpret_cast<const float4*>(sWr + k * DDIM + d0);
            p[k] = wv.x * mx.x + wv.y * mx.y + wv.z * mx.z + wv.w * mx.w;
        }

        // fold upper half-warp into lower (xor 16), then stage 256 rows
        #pragma unroll
        for (int k = 0; k < WRK; k++)
            p[k] += __shfl_xor_sync(FULL, p[k], 16);

        if (lane < 16) {
            float* row = sP + (warp * 16 + lane) * PSTRIDE;
            #pragma unroll
            for (int k = 0; k < WRK; k++) row[k] = p[k];
        }
        __syncthreads();

        // ---- cross-warp reduce: warp w handles k = w and k = w + 12 ----
        if (warp < 12) {
            #pragma unroll
            for (int h = 0; h < 2; h++) {
                int k = warp + h * 12;
                float s = 0.0f;
                #pragma unroll
                for (int r = 0; r < 8; r++)
                    s += sP[(lane + 32 * r) * PSTRIDE + k];
                #pragma unroll
                for (int o = 16; o > 0; o >>= 1)
                    s += __shfl_xor_sync(FULL, s, o);
                if (lane == 0) sRaw[k] = s + __ldg(br + k);
            }
        }
        __syncthreads();

        // ---- warp 0: softmaxes + sinkhorn -> M[4][4] ----
        if (warp == 0) {
            // quad softmax: lanes 0-3 -> pre[j], lanes 4-7 -> post[i]
            float v = sRaw[lane & 7];
            float mq = v;
            mq = fmaxf(mq, __shfl_xor_sync(FULL, mq, 1));
            mq = fmaxf(mq, __shfl_xor_sync(FULL, mq, 2));
            float e = __expf(v - mq);
            float sq = e;
            sq += __shfl_xor_sync(FULL, sq, 1);
            sq += __shfl_xor_sync(FULL, sq, 2);
            float soft = e / sq;

            // sinkhorn on 4x4: lane l<16 holds element (i,j)
            int l  = lane & 15;
            int i4 = l >> 2;
            int j4 = l & 3;
            float wv = __expf(sRaw[8 + l] + (i4 == j4 ? 2.0f : -2.0f));
            #pragma unroll
            for (int it = 0; it < 4; it++) {
                float rs = wv;                      // row sum (over j)
                rs += __shfl_xor_sync(FULL, rs, 1);
                rs += __shfl_xor_sync(FULL, rs, 2);
                wv = wv / fmaxf(rs, EPSV);
                float cs = wv;                      // col sum (over i)
                cs += __shfl_xor_sync(FULL, cs, 4);
                cs += __shfl_xor_sync(FULL, cs, 8);
                wv = wv / fmaxf(cs, EPSV);
            }
            float post_i = __shfl_sync(FULL, soft, 4 + i4);
            float pre_j  = __shfl_sync(FULL, soft, j4);
            if (lane < 16) sM[lane] = wv + post_i * pre_j;
        }
        __syncthreads();

        // ---- mix and store: out[i] = sum_j M[i][j] * x[j] ----
        #pragma unroll
        for (int i = 0; i < WSTREAMS; i++) {
            float4 Mi = *reinterpret_cast<const float4*>(sM + i * 4); // broadcast
            float4 o;
            o.x = Mi.x * xv[0].x + Mi.y * xv[1].x + Mi.z * xv[2].x + Mi.w * xv[3].x;
            o.y = Mi.x * xv[0].y + Mi.y * xv[1].y + Mi.z * xv[2].y + Mi.w * xv[3].y;
            o.z = Mi.x * xv[0].z + Mi.y * xv[1].z + Mi.z * xv[2].z + Mi.w * xv[3].z;
            o.w = Mi.x * xv[0].w + Mi.y * xv[1].w + Mi.z * xv[2].w + Mi.w * xv[3].w;
            __stcs(reinterpret_cast<float4*>(ot + i * DDIM + d0), o);
        }
        // next iteration's sP writes are gated by the syncthreads above the
        // reduce phase; sM reads here are ordered before the next sRaw/sM write.
    }
}

extern "C" void kernel_launch(void* const* d_in, const int* in_sizes, int n_in,
                              void* d_out, int out_size)
{
    const float* x  = (const float*)d_in[0];
    const float* Wr = (const float*)d_in[1];
    const float* br = (const float*)d_in[2];
    float* out = (float*)d_out;

    int ntok = in_sizes[0] / (WSTREAMS * DDIM);   // 8192

    cudaFuncSetAttribute(mchc_fused_kernel,
                         cudaFuncAttributeMaxDynamicSharedMemorySize, SMEM_BYTES);

    int sms = 148;
    int dev = 0;
    if (cudaGetDevice(&dev) == cudaSuccess) {
        int v = 0;
        if (cudaDeviceGetAttribute(&v, cudaDevAttrMultiProcessorCount, dev) == cudaSuccess && v > 0)
            sms = v;
    }
    int grid = (ntok < sms) ? ntok : sms;

    mchc_fused_kernel<<<grid, THREADS, SMEM_BYTES>>>(x, Wr, br, out, ntok);
}

// round 3
// speedup vs baseline: 1.3521x; 1.3521x over previous
#include <cuda_runtime.h>
#include <cuda_bf16.h>

// ManifoldConstrainedHyperConnection — fused, token-batched (G=2),
// multi-value butterfly warp reduction (sm_103 has no redux.f32).
//
// Per token: raw[24] = mean_w(x) @ Wr^T + b; pre/post = softmax(raw[0:4]/[4:8]);
// res = sinkhorn4(exp(raw[8:24] + (+2 diag / -2 off))); M = res + post⊗pre;
// out[i,:] = sum_j M[i][j] x[j,:].
//
// 1 CTA/SM, 512 threads, Wr (192KB) in smem. Each thread owns a 4-float
// d-slice. 48 router partials per token-pair are reduced with a 62-shuffle
// butterfly transpose; warp 0 does the tiny serial math while other warps
// prefetch the next token pair.

#define WRK 24
#define DDIM 2048
#define WS 4
#define THREADS 512
#define NW 16
#define G 2
#define EPSV 1e-6f

#define SMEM_WR (WRK * DDIM)          // 49152 floats
#define SP_STRIDE 49
#define SMEM_SP (NW * SP_STRIDE)
#define SMEM_FLOATS (SMEM_WR + SMEM_SP + 48 + 32)
#define SMEM_BYTES (SMEM_FLOATS * 4)

__device__ __forceinline__ float4 ld_cs4(const float* p) {
    return __ldcs(reinterpret_cast<const float4*>(p));
}

#define FULLM 0xffffffffu

// one butterfly step: values r[0..n-1] -> r[0..n/2-1]; lane bit `o` selects
// which half of the value-index space this lane keeps accumulating.
#define BFLY_STEP(r, n, o)                                              \
    {                                                                   \
        const bool hi_ = (lane & (o)) != 0;                             \
        _Pragma("unroll")                                               \
        for (int v_ = 0; v_ < (n) / 2; v_++) {                          \
            float mine_  = hi_ ? r[v_ + (n) / 2] : r[v_];               \
            float other_ = hi_ ? r[v_] : r[v_ + (n) / 2];               \
            r[v_] = mine_ + __shfl_xor_sync(FULLM, other_, (o));        \
        }                                                               \
    }

__global__ void __launch_bounds__(THREADS, 1)
mchc_kernel(const float* __restrict__ x, const float* __restrict__ Wr,
            const float* __restrict__ br, float* __restrict__ out, int ntok)
{
    extern __shared__ float sm[];
    float* sWr  = sm;
    float* sP   = sm + SMEM_WR;
    float* sRaw = sP + SMEM_SP;
    float* sM   = sRaw + 48;

    const int tid  = threadIdx.x;
    const int lane = tid & 31;
    const int warp = tid >> 5;
    const int d0   = tid * 4;

    // stage W_router into smem once
    for (int i = tid * 4; i < SMEM_WR; i += THREADS * 4)
        *reinterpret_cast<float4*>(sWr + i) = *reinterpret_cast<const float4*>(Wr + i);
    __syncthreads();

    const int ngroups = (ntok + G - 1) / G;
    int g = blockIdx.x;
    if (g >= ngroups) return;

    // prologue: first group's x slices
    float4 xv[G][WS];
    {
        int n0 = g * G;
        #pragma unroll
        for (int t = 0; t < G; t++) {
            bool ok = (n0 + t) < ntok;
            const float* p = x + (size_t)(n0 + t) * (WS * DDIM) + d0;
            #pragma unroll
            for (int w = 0; w < WS; w++)
                xv[t][w] = ok ? ld_cs4(p + w * DDIM) : make_float4(0.f, 0.f, 0.f, 0.f);
        }
    }

    for (; g < ngroups; g += gridDim.x) {
        const int n0 = g * G;

        // means over streams
        float4 mx[G];
        #pragma unroll
        for (int t = 0; t < G; t++) {
            mx[t].x = (xv[t][0].x + xv[t][1].x + xv[t][2].x + xv[t][3].x) * 0.25f;
            mx[t].y = (xv[t][0].y + xv[t][1].y + xv[t][2].y + xv[t][3].y) * 0.25f;
            mx[t].z = (xv[t][0].z + xv[t][1].z + xv[t][2].z + xv[t][3].z) * 0.25f;
            mx[t].w = (xv[t][0].w + xv[t][1].w + xv[t][2].w + xv[t][3].w) * 0.25f;
        }

        // ---- set A: values v = 2k+t for k = 0..15 (32 values) ----
        float a[32];
        #pragma unroll
        for (int k = 0; k < 16; k++) {
            float4 wv = *reinterpret_cast<const float4*>(sWr + k * DDIM + d0);
            a[2*k+0] = wv.x*mx[0].x + wv.y*mx[0].y + wv.z*mx[0].z + wv.w*mx[0].w;
            a[2*k+1] = wv.x*mx[1].x + wv.y*mx[1].y + wv.z*mx[1].z + wv.w*mx[1].w;
        }
        BFLY_STEP(a, 32, 16)
        BFLY_STEP(a, 16, 8)
        BFLY_STEP(a, 8, 4)
        BFLY_STEP(a, 4, 2)
        BFLY_STEP(a, 2, 1)
        // a[0] on lane l = full warp sum of value l  (k = l>>1, t = l&1)

        // ---- set B: values 32 + (2(k-16)+t) for k = 16..23 (16 values) ----
        float b[16];
        #pragma unroll
        for (int k = 16; k < 24; k++) {
            float4 wv = *reinterpret_cast<const float4*>(sWr + k * DDIM + d0);
            b[2*(k-16)+0] = wv.x*mx[0].x + wv.y*mx[0].y + wv.z*mx[0].z + wv.w*mx[0].w;
            b[2*(k-16)+1] = wv.x*mx[1].x + wv.y*mx[1].y + wv.z*mx[1].z + wv.w*mx[1].w;
        }
        #pragma unroll
        for (int v = 0; v < 16; v++)
            b[v] += __shfl_xor_sync(FULLM, b[v], 16);
        BFLY_STEP(b, 16, 8)
        BFLY_STEP(b, 8, 4)
        BFLY_STEP(b, 4, 2)
        BFLY_STEP(b, 2, 1)
        // b[0] on lane l = full warp sum of value (l & 15)  (k = 16+((l&15)>>1), t = l&1)

        // stage per-warp partials (16 warps x 48 floats)
        sP[warp * SP_STRIDE + lane] = a[0];
        if (lane < 16) sP[warp * SP_STRIDE + 32 + lane] = b[0];
        __syncthreads();                                     // (A)

        // prefetch next group's x while warp 0 does the serial math
        const int gn = g + gridDim.x;
        float4 xn[G][WS];
        if (gn < ngroups) {
            int m0 = gn * G;
            #pragma unroll
            for (int t = 0; t < G; t++) {
                bool ok = (m0 + t) < ntok;
                const float* p = x + (size_t)(m0 + t) * (WS * DDIM) + d0;
                #pragma unroll
                for (int w = 0; w < WS; w++)
                    xn[t][w] = ok ? ld_cs4(p + w * DDIM) : make_float4(0.f, 0.f, 0.f, 0.f);
            }
        }

        if (warp == 0) {
            // cross-warp reduce (conflict-free: consecutive lanes -> consecutive addrs)
            {
                int k = lane >> 1, t = lane & 1;
                float acc = __ldg(br + k);
                #pragma unroll
                for (int w = 0; w < NW; w++) acc += sP[w * SP_STRIDE + lane];
                sRaw[t * WRK + k] = acc;
            }
            if (lane < 16) {
                int k = 16 + (lane >> 1), t = lane & 1;
                float acc = __ldg(br + k);
                #pragma unroll
                for (int w = 0; w < NW; w++) acc += sP[w * SP_STRIDE + 32 + lane];
                sRaw[t * WRK + k] = acc;
            }
            __syncwarp();

            // scalar softmaxes + sinkhorn; lanes 0-15 token 0, lanes 16-31 token 1
            const int t = lane >> 4;
            const float* rw = sRaw + t * WRK;

            float p0 = rw[0], p1 = rw[1], p2 = rw[2], p3 = rw[3];
            float mp = fmaxf(fmaxf(p0, p1), fmaxf(p2, p3));
            p0 = __expf(p0 - mp); p1 = __expf(p1 - mp);
            p2 = __expf(p2 - mp); p3 = __expf(p3 - mp);
            float isp = __fdividef(1.f, p0 + p1 + p2 + p3);
            p0 *= isp; p1 *= isp; p2 *= isp; p3 *= isp;

            float q0 = rw[4], q1 = rw[5], q2 = rw[6], q3 = rw[7];
            float mq = fmaxf(fmaxf(q0, q1), fmaxf(q2, q3));
            q0 = __expf(q0 - mq); q1 = __expf(q1 - mq);
            q2 = __expf(q2 - mq); q3 = __expf(q3 - mq);
            float isq = __fdividef(1.f, q0 + q1 + q2 + q3);
            q0 *= isq; q1 *= isq; q2 *= isq; q3 *= isq;

            float av[16];
            #pragma unroll
            for (int i = 0; i < 4; i++)
                #pragma unroll
                for (int j = 0; j < 4; j++)
                    av[i * 4 + j] = __expf(rw[8 + i * 4 + j] + (i == j ? 2.0f : -2.0f));

            #pragma unroll
            for (int it = 0; it < 4; it++) {
                #pragma unroll
                for (int i = 0; i < 4; i++) {
                    float rs  = av[i*4] + av[i*4+1] + av[i*4+2] + av[i*4+3];
                    float inv = __fdividef(1.f, fmaxf(rs, EPSV));
                    av[i*4] *= inv; av[i*4+1] *= inv; av[i*4+2] *= inv; av[i*4+3] *= inv;
                }
                #pragma unroll
                for (int j = 0; j < 4; j++) {
                    float cs  = av[j] + av[4+j] + av[8+j] + av[12+j];
                    float inv = __fdividef(1.f, fmaxf(cs, EPSV));
                    av[j] *= inv; av[4+j] *= inv; av[8+j] *= inv; av[12+j] *= inv;
                }
            }

            if ((lane & 15) == 0) {
                const float pre[4]  = {p0, p1, p2, p3};
                const float post[4] = {q0, q1, q2, q3};
                #pragma unroll
                for (int i = 0; i < 4; i++) {
                    float4 mrow;
                    mrow.x = av[i*4+0] + post[i] * pre[0];
                    mrow.y = av[i*4+1] + post[i] * pre[1];
                    mrow.z = av[i*4+2] + post[i] * pre[2];
                    mrow.w = av[i*4+3] + post[i] * pre[3];
                    *reinterpret_cast<float4*>(sM + t * 16 + i * 4) = mrow;
                }
            }
        }
        __syncthreads();                                     // (B)

        // mix + store
        #pragma unroll
        for (int t = 0; t < G; t++) {
            if ((n0 + t) < ntok) {
                float* o = out + (size_t)(n0 + t) * (WS * DDIM) + d0;
                #pragma unroll
                for (int i = 0; i < WS; i++) {
                    float4 Mi = *reinterpret_cast<const float4*>(sM + t * 16 + i * 4);
                    float4 ov;
                    ov.x = Mi.x * xv[t][0].x + Mi.y * xv[t][1].x + Mi.z * xv[t][2].x + Mi.w * xv[t][3].x;
                    ov.y = Mi.x * xv[t][0].y + Mi.y * xv[t][1].y + Mi.z * xv[t][2].y + Mi.w * xv[t][3].y;
                    ov.z = Mi.x * xv[t][0].z + Mi.y * xv[t][1].z + Mi.z * xv[t][2].z + Mi.w * xv[t][3].z;
                    ov.w = Mi.x * xv[t][0].w + Mi.y * xv[t][1].w + Mi.z * xv[t][2].w + Mi.w * xv[t][3].w;
                    __stcs(reinterpret_cast<float4*>(o + i * DDIM), ov);
                }
            }
        }

        // rotate prefetched registers in
        #pragma unroll
        for (int t = 0; t < G; t++)
            #pragma unroll
            for (int w = 0; w < WS; w++)
                xv[t][w] = xn[t][w];
    }
}

extern "C" void kernel_launch(void* const* d_in, const int* in_sizes, int n_in,
                              void* d_out, int out_size)
{
    const float* x  = (const float*)d_in[0];
    const float* Wr = (const float*)d_in[1];
    const float* br = (const float*)d_in[2];
    float* out = (float*)d_out;

    int ntok = in_sizes[0] / (WS * DDIM);   // 8192

    cudaFuncSetAttribute(mchc_kernel,
                         cudaFuncAttributeMaxDynamicSharedMemorySize, SMEM_BYTES);

    int sms = 148, dev = 0;
    if (cudaGetDevice(&dev) == cudaSuccess) {
        int v = 0;
        if (cudaDeviceGetAttribute(&v, cudaDevAttrMultiProcessorCount, dev) == cudaSuccess && v > 0)
            sms = v;
    }
    int ngroups = (ntok + G - 1) / G;
    int grid = (ngroups < sms) ? ngroups : sms;

    mchc_kernel<<<grid, THREADS, SMEM_BYTES>>>(x, Wr, br, out, ntok);
}

// round 4
// speedup vs baseline: 1.3823x; 1.0224x over previous
#include <cuda_runtime.h>
#include <cuda_bf16.h>

// ManifoldConstrainedHyperConnection — fused, G=4 token batching.
// x is NOT held in registers across the group: read once (ld.cg) for the
// stream-mean, re-read from L2 for the mix. This frees registers for G=4,
// quartering the W_router crossbar cost per token.
//
// 1 CTA/SM, 512 threads, Wr (192KB) in smem, thread owns a 4-float d-slice.
// 96 router partials/group reduced by 3x 32-value shuffle butterflies.
// Warps 0-2 cross-warp reduce (named barrier), warps 0-1 run the scalar
// softmax+sinkhorn (2 tokens each) while everyone's x re-read is in flight.

#define WRK 24
#define DDIM 2048
#define WS 4
#define THREADS 512
#define NW 16
#define G 4
#define EPSV 1e-6f

#define SMEM_WR (WRK * DDIM)            // 49152 floats
#define SP_STRIDE 100
#define SMEM_SP (NW * SP_STRIDE)        // 1600 floats
#define SMEM_FLOATS (SMEM_WR + SMEM_SP + 96 + 64)
#define SMEM_BYTES (SMEM_FLOATS * 4)

#define FULLM 0xffffffffu

__device__ __forceinline__ float4 ld_cg4(const float* p) {
    return __ldcg(reinterpret_cast<const float4*>(p));
}

// butterfly step: values r[0..n-1] -> r[0..n/2-1]
#define BFLY_STEP(r, n, o)                                              \
    {                                                                   \
        const bool hi_ = (lane & (o)) != 0;                             \
        _Pragma("unroll")                                               \
        for (int v_ = 0; v_ < (n) / 2; v_++) {                          \
            float mine_  = hi_ ? r[v_ + (n) / 2] : r[v_];               \
            float other_ = hi_ ? r[v_] : r[v_ + (n) / 2];               \
            r[v_] = mine_ + __shfl_xor_sync(FULLM, other_, (o));        \
        }                                                               \
    }

__global__ void __launch_bounds__(THREADS, 1)
mchc_kernel(const float* __restrict__ x, const float* __restrict__ Wr,
            const float* __restrict__ br, float* __restrict__ out, int ntok)
{
    extern __shared__ float sm[];
    float* sWr  = sm;
    float* sP   = sm + SMEM_WR;
    float* sRaw = sP + SMEM_SP;      // 96 floats: sRaw[4k+t]
    float* sM   = sRaw + 96;         // 64 floats: sM[t*16 + i*4 + j]

    const int tid  = threadIdx.x;
    const int lane = tid & 31;
    const int warp = tid >> 5;
    const int d0   = tid * 4;

    // stage W_router into smem once
    for (int i = tid * 4; i < SMEM_WR; i += THREADS * 4)
        *reinterpret_cast<float4*>(sWr + i) = *reinterpret_cast<const float4*>(Wr + i);
    __syncthreads();

    const int ngroups = (ntok + G - 1) / G;

    for (int g = blockIdx.x; g < ngroups; g += gridDim.x) {
        const int n0 = g * G;

        // ---- pass 1: stream means (x read once, L2-cached, not kept) ----
        float4 mx[G];
        #pragma unroll
        for (int t = 0; t < G; t++) {
            mx[t] = make_float4(0.f, 0.f, 0.f, 0.f);
            if (n0 + t < ntok) {
                const float* p = x + (size_t)(n0 + t) * (WS * DDIM) + d0;
                #pragma unroll
                for (int w = 0; w < WS; w++) {
                    float4 v = ld_cg4(p + w * DDIM);
                    mx[t].x += v.x; mx[t].y += v.y; mx[t].z += v.z; mx[t].w += v.w;
                }
                mx[t].x *= 0.25f; mx[t].y *= 0.25f; mx[t].z *= 0.25f; mx[t].w *= 0.25f;
            }
        }

        // ---- router partials: 3 sets of 32 values (v = 4k+t) ----
        float res[3];
        #pragma unroll
        for (int s = 0; s < 3; s++) {
            float a[32];
            #pragma unroll
            for (int kk = 0; kk < 8; kk++) {
                const int k = 8 * s + kk;
                float4 wv = *reinterpret_cast<const float4*>(sWr + k * DDIM + d0);
                #pragma unroll
                for (int t = 0; t < G; t++)
                    a[kk * 4 + t] = wv.x * mx[t].x + wv.y * mx[t].y +
                                    wv.z * mx[t].z + wv.w * mx[t].w;
            }
            BFLY_STEP(a, 32, 16)
            BFLY_STEP(a, 16, 8)
            BFLY_STEP(a, 8, 4)
            BFLY_STEP(a, 4, 2)
            BFLY_STEP(a, 2, 1)
            res[s] = a[0];   // lane l holds sum of value 32s + l
        }
        #pragma unroll
        for (int s = 0; s < 3; s++)
            sP[warp * SP_STRIDE + 32 * s + lane] = res[s];
        __syncthreads();                                     // (A)

        // ---- all warps: issue x re-read now (L2 hit), consumed after (B) ----
        float4 xr[G][WS];
        #pragma unroll
        for (int t = 0; t < G; t++) {
            if (n0 + t < ntok) {
                const float* p = x + (size_t)(n0 + t) * (WS * DDIM) + d0;
                #pragma unroll
                for (int w = 0; w < WS; w++)
                    xr[t][w] = ld_cg4(p + w * DDIM);
            }
        }

        // ---- warps 0-2: cross-warp reduce one 32-value set each ----
        if (warp < 3) {
            const int v = 32 * warp + lane;        // v = 4k + t
            float acc = __ldg(br + (v >> 2));
            #pragma unroll
            for (int w = 0; w < NW; w++)
                acc += sP[w * SP_STRIDE + v];
            sRaw[v] = acc;
            asm volatile("bar.sync 1, 96;" ::: "memory");   // warps 0-2 only
        }

        // ---- warps 0-1: scalar softmax + sinkhorn, 2 tokens per warp ----
        if (warp < 2) {
            const int t = warp * 2 + (lane >> 4);   // token 0..3

            float p0 = sRaw[0*4+t], p1 = sRaw[1*4+t], p2 = sRaw[2*4+t], p3 = sRaw[3*4+t];
            float mp = fmaxf(fmaxf(p0, p1), fmaxf(p2, p3));
            p0 = __expf(p0 - mp); p1 = __expf(p1 - mp);
            p2 = __expf(p2 - mp); p3 = __expf(p3 - mp);
            float isp = __fdividef(1.f, p0 + p1 + p2 + p3);
            p0 *= isp; p1 *= isp; p2 *= isp; p3 *= isp;

            float q0 = sRaw[4*4+t], q1 = sRaw[5*4+t], q2 = sRaw[6*4+t], q3 = sRaw[7*4+t];
            float mq = fmaxf(fmaxf(q0, q1), fmaxf(q2, q3));
            q0 = __expf(q0 - mq); q1 = __expf(q1 - mq);
            q2 = __expf(q2 - mq); q3 = __expf(q3 - mq);
            float isq = __fdividef(1.f, q0 + q1 + q2 + q3);
            q0 *= isq; q1 *= isq; q2 *= isq; q3 *= isq;

            float av[16];
            #pragma unroll
            for (int i = 0; i < 4; i++)
                #pragma unroll
                for (int j = 0; j < 4; j++)
                    av[i*4+j] = __expf(sRaw[(8 + i*4 + j)*4 + t] + (i == j ? 2.0f : -2.0f));

            #pragma unroll
            for (int it = 0; it < 4; it++) {
                #pragma unroll
                for (int i = 0; i < 4; i++) {
                    float rs  = av[i*4] + av[i*4+1] + av[i*4+2] + av[i*4+3];
                    float inv = __fdividef(1.f, fmaxf(rs, EPSV));
                    av[i*4] *= inv; av[i*4+1] *= inv; av[i*4+2] *= inv; av[i*4+3] *= inv;
                }
                #pragma unroll
                for (int j = 0; j < 4; j++) {
                    float cs  = av[j] + av[4+j] + av[8+j] + av[12+j];
                    float inv = __fdividef(1.f, fmaxf(cs, EPSV));
                    av[j] *= inv; av[4+j] *= inv; av[8+j] *= inv; av[12+j] *= inv;
                }
            }

            if ((lane & 15) == 0) {
                const float pre[4]  = {p0, p1, p2, p3};
                const float post[4] = {q0, q1, q2, q3};
                #pragma unroll
                for (int i = 0; i < 4; i++) {
                    float4 mrow;
                    mrow.x = av[i*4+0] + post[i] * pre[0];
                    mrow.y = av[i*4+1] + post[i] * pre[1];
                    mrow.z = av[i*4+2] + post[i] * pre[2];
                    mrow.w = av[i*4+3] + post[i] * pre[3];
                    *reinterpret_cast<float4*>(sM + t * 16 + i * 4) = mrow;
                }
            }
        }
        __syncthreads();                                     // (B)

        // ---- mix + store ----
        #pragma unroll
        for (int t = 0; t < G; t++) {
            if (n0 + t < ntok) {
                float* o = out + (size_t)(n0 + t) * (WS * DDIM) + d0;
                #pragma unroll
                for (int i = 0; i < WS; i++) {
                    float4 Mi = *reinterpret_cast<const float4*>(sM + t * 16 + i * 4);
                    float4 ov;
                    ov.x = Mi.x*xr[t][0].x + Mi.y*xr[t][1].x + Mi.z*xr[t][2].x + Mi.w*xr[t][3].x;
                    ov.y = Mi.x*xr[t][0].y + Mi.y*xr[t][1].y + Mi.z*xr[t][2].y + Mi.w*xr[t][3].y;
                    ov.z = Mi.x*xr[t][0].z + Mi.y*xr[t][1].z + Mi.z*xr[t][2].z + Mi.w*xr[t][3].z;
                    ov.w = Mi.x*xr[t][0].w + Mi.y*xr[t][1].w + Mi.z*xr[t][2].w + Mi.w*xr[t][3].w;
                    __stcs(reinterpret_cast<float4*>(o + i * DDIM), ov);
                }
            }
        }
        __syncthreads();   // protect sP/sRaw/sM from next iteration's writes
    }
}

extern "C" void kernel_launch(void* const* d_in, const int* in_sizes, int n_in,
                              void* d_out, int out_size)
{
    const float* x  = (const float*)d_in[0];
    const float* Wr = (const float*)d_in[1];
    const float* br = (const float*)d_in[2];
    float* out = (float*)d_out;

    int ntok = in_sizes[0] / (WS * DDIM);   // 8192

    cudaFuncSetAttribute(mchc_kernel,
                         cudaFuncAttributeMaxDynamicSharedMemorySize, SMEM_BYTES);

    int sms = 148, dev = 0;
    if (cudaGetDevice(&dev) == cudaSuccess) {
        int v = 0;
        if (cudaDeviceGetAttribute(&v, cudaDevAttrMultiProcessorCount, dev) == cudaSuccess && v > 0)
            sms = v;
    }
    int ngroups = (ntok + G - 1) / G;
    int grid = (ngroups < sms) ? ngroups : sms;

    mchc_kernel<<<grid, THREADS, SMEM_BYTES>>>(x, Wr, br, out, ntok);
}

// round 5
// speedup vs baseline: 1.6749x; 1.2116x over previous
#include <cuda_runtime.h>
#include <cuda_bf16.h>

// ManifoldConstrainedHyperConnection — fused, G=4, L2-prefetch pipelined.
//
// Per token: raw[24] = mean_w(x) @ Wr^T + b; pre/post = softmax(raw[0:4]/[4:8]);
// res = sinkhorn4(exp(raw[8:24] + (+2 diag/-2 off))); M = res + post x pre;
// out[i,:] = sum_j M[i][j] x[j,:].
//
// 1 CTA/SM, 512 threads, Wr (192KB) in smem, each thread owns a 4-float
// d-slice. Group g+stride's x is warmed into L2 via prefetch.global.L2 while
// group g finishes, so the pass-1 read + mix re-read are both L2 hits.
// 96 router partials/group reduced by 3x 32-value shuffle butterflies;
// warps 0-2 cross-warp reduce (named barrier); warps 0-1 run the scalar
// softmax+sinkhorn.

#define WRK 24
#define DDIM 2048
#define WS 4
#define THREADS 512
#define NW 16
#define G 4
#define EPSV 1e-6f

#define SMEM_WR (WRK * DDIM)            // 49152 floats
#define SP_STRIDE 100
#define SMEM_SP (NW * SP_STRIDE)        // 1600 floats
#define SMEM_FLOATS (SMEM_WR + SMEM_SP + 96 + 64)
#define SMEM_BYTES (SMEM_FLOATS * 4)

#define FULLM 0xffffffffu

__device__ __forceinline__ float4 ld_cg4(const float* p) {
    return __ldcg(reinterpret_cast<const float4*>(p));
}

// butterfly step: values r[0..n-1] -> r[0..n/2-1]
#define BFLY_STEP(r, n, o)                                              \
    {                                                                   \
        const bool hi_ = (lane & (o)) != 0;                             \
        _Pragma("unroll")                                               \
        for (int v_ = 0; v_ < (n) / 2; v_++) {                          \
            float mine_  = hi_ ? r[v_ + (n) / 2] : r[v_];               \
            float other_ = hi_ ? r[v_] : r[v_ + (n) / 2];               \
            r[v_] = mine_ + __shfl_xor_sync(FULLM, other_, (o));        \
        }                                                               \
    }

__global__ void __launch_bounds__(THREADS, 1)
mchc_kernel(const float* __restrict__ x, const float* __restrict__ Wr,
            const float* __restrict__ br, float* __restrict__ out, int ntok)
{
    extern __shared__ float sm[];
    float* sWr  = sm;
    float* sP   = sm + SMEM_WR;
    float* sRaw = sP + SMEM_SP;      // 96 floats, layout raw-index = 4k + t
    float* sM   = sRaw + 96;         // 64 floats: sM[t*16 + i*4 + j]

    const int tid  = threadIdx.x;
    const int lane = tid & 31;
    const int warp = tid >> 5;
    const int d0   = tid * 4;

    // stage W_router into smem once
    for (int i = tid * 4; i < SMEM_WR; i += THREADS * 4)
        *reinterpret_cast<float4*>(sWr + i) = *reinterpret_cast<const float4*>(Wr + i);
    __syncthreads();

    const int ngroups = (ntok + G - 1) / G;

    for (int g = blockIdx.x; g < ngroups; g += gridDim.x) {
        const int n0 = g * G;

        // ---- A: pass-1 read (L2-warm from prefetch) -> stream means ----
        float4 mx[G];
        {
            float4 xa[G * WS];
            #pragma unroll
            for (int t = 0; t < G; t++) {
                if (n0 + t < ntok) {
                    const float* p = x + (size_t)(n0 + t) * (WS * DDIM) + d0;
                    #pragma unroll
                    for (int w = 0; w < WS; w++)
                        xa[t * 4 + w] = ld_cg4(p + w * DDIM);
                } else {
                    #pragma unroll
                    for (int w = 0; w < WS; w++)
                        xa[t * 4 + w] = make_float4(0.f, 0.f, 0.f, 0.f);
                }
            }
            #pragma unroll
            for (int t = 0; t < G; t++) {
                mx[t].x = (xa[t*4].x + xa[t*4+1].x + xa[t*4+2].x + xa[t*4+3].x) * 0.25f;
                mx[t].y = (xa[t*4].y + xa[t*4+1].y + xa[t*4+2].y + xa[t*4+3].y) * 0.25f;
                mx[t].z = (xa[t*4].z + xa[t*4+1].z + xa[t*4+2].z + xa[t*4+3].z) * 0.25f;
                mx[t].w = (xa[t*4].w + xa[t*4+1].w + xa[t*4+2].w + xa[t*4+3].w) * 0.25f;
            }
        }

        // ---- B: router partials, 3 sets of 32 values (v = 4k + t) ----
        float res[3];
        #pragma unroll
        for (int s = 0; s < 3; s++) {
            float a[32];
            #pragma unroll
            for (int kk = 0; kk < 8; kk++) {
                const int k = 8 * s + kk;
                float4 wv = *reinterpret_cast<const float4*>(sWr + k * DDIM + d0);
                #pragma unroll
                for (int t = 0; t < G; t++)
                    a[kk * 4 + t] = wv.x * mx[t].x + wv.y * mx[t].y +
                                    wv.z * mx[t].z + wv.w * mx[t].w;
            }
            BFLY_STEP(a, 32, 16)
            BFLY_STEP(a, 16, 8)
            BFLY_STEP(a, 8, 4)
            BFLY_STEP(a, 4, 2)
            BFLY_STEP(a, 2, 1)
            res[s] = a[0];   // lane l holds warp-sum of value 32s + l
        }
        #pragma unroll
        for (int s = 0; s < 3; s++)
            sP[warp * SP_STRIDE + 32 * s + lane] = res[s];
        __syncthreads();                                     // bar A

        // ---- C: warm next group's x into L2 (no registers consumed) ----
        {
            const int gn = g + gridDim.x;
            if (gn < ngroups) {
                // group = G*WS*DDIM*4 bytes = 131072 B = 512 threads * 256 B
                const char* pb = reinterpret_cast<const char*>(
                                     x + (size_t)gn * G * (WS * DDIM)) + tid * 256;
                asm volatile("prefetch.global.L2 [%0];" :: "l"(pb));
                asm volatile("prefetch.global.L2 [%0];" :: "l"(pb + 128));
            }
        }

        // ---- D: warps 0-2 cross-warp reduce; warps 0-1 softmax+sinkhorn ----
        if (warp < 3) {
            // value v = 32*warp + lane  (= 4k + t, k = 8*warp + lane/4)
            float acc = __ldg(br + 8 * warp + (lane >> 2));
            #pragma unroll
            for (int w = 0; w < NW; w++)
                acc += sP[w * SP_STRIDE + 32 * warp + lane];
            sRaw[32 * warp + lane] = acc;
            asm volatile("bar.sync 1, 96;" ::: "memory");   // warps 0-2 only
        }

        if (warp < 2) {
            const int t = warp * 2 + (lane >> 4);   // token 0..3

            float p0 = sRaw[0*4+t], p1 = sRaw[1*4+t], p2 = sRaw[2*4+t], p3 = sRaw[3*4+t];
            float mp = fmaxf(fmaxf(p0, p1), fmaxf(p2, p3));
            p0 = __expf(p0 - mp); p1 = __expf(p1 - mp);
            p2 = __expf(p2 - mp); p3 = __expf(p3 - mp);
            float isp = __fdividef(1.f, p0 + p1 + p2 + p3);
            p0 *= isp; p1 *= isp; p2 *= isp; p3 *= isp;

            float q0 = sRaw[4*4+t], q1 = sRaw[5*4+t], q2 = sRaw[6*4+t], q3 = sRaw[7*4+t];
            float mq = fmaxf(fmaxf(q0, q1), fmaxf(q2, q3));
            q0 = __expf(q0 - mq); q1 = __expf(q1 - mq);
            q2 = __expf(q2 - mq); q3 = __expf(q3 - mq);
            float isq = __fdividef(1.f, q0 + q1 + q2 + q3);
            q0 *= isq; q1 *= isq; q2 *= isq; q3 *= isq;

            float av[16];
            #pragma unroll
            for (int i = 0; i < 4; i++)
                #pragma unroll
                for (int j = 0; j < 4; j++)
                    av[i*4+j] = __expf(sRaw[(8 + i*4 + j)*4 + t] + (i == j ? 2.0f : -2.0f));

            #pragma unroll
            for (int it = 0; it < 4; it++) {
                #pragma unroll
                for (int i = 0; i < 4; i++) {
                    float rs  = av[i*4] + av[i*4+1] + av[i*4+2] + av[i*4+3];
                    float inv = __fdividef(1.f, fmaxf(rs, EPSV));
                    av[i*4] *= inv; av[i*4+1] *= inv; av[i*4+2] *= inv; av[i*4+3] *= inv;
                }
                #pragma unroll
                for (int j = 0; j < 4; j++) {
                    float cs  = av[j] + av[4+j] + av[8+j] + av[12+j];
                    float inv = __fdividef(1.f, fmaxf(cs, EPSV));
                    av[j] *= inv; av[4+j] *= inv; av[8+j] *= inv; av[12+j] *= inv;
                }
            }

            if ((lane & 15) == 0) {
                const float pre[4]  = {p0, p1, p2, p3};
                const float post[4] = {q0, q1, q2, q3};
                #pragma unroll
                for (int i = 0; i < 4; i++) {
                    float4 mrow;
                    mrow.x = av[i*4+0] + post[i] * pre[0];
                    mrow.y = av[i*4+1] + post[i] * pre[1];
                    mrow.z = av[i*4+2] + post[i] * pre[2];
                    mrow.w = av[i*4+3] + post[i] * pre[3];
                    *reinterpret_cast<float4*>(sM + t * 16 + i * 4) = mrow;
                }
            }
        }
        __syncthreads();                                     // bar B

        // ---- F: mix + store (x re-read is an L2 hit) ----
        #pragma unroll
        for (int t = 0; t < G; t++) {
            if (n0 + t < ntok) {
                const float* p = x + (size_t)(n0 + t) * (WS * DDIM) + d0;
                float*       o = out + (size_t)(n0 + t) * (WS * DDIM) + d0;
                float4 x0 = ld_cg4(p);
                float4 x1 = ld_cg4(p + DDIM);
                float4 x2 = ld_cg4(p + 2 * DDIM);
                float4 x3 = ld_cg4(p + 3 * DDIM);
                #pragma unroll
                for (int i = 0; i < WS; i++) {
                    float4 Mi = *reinterpret_cast<const float4*>(sM + t * 16 + i * 4);
                    float4 ov;
                    ov.x = Mi.x*x0.x + Mi.y*x1.x + Mi.z*x2.x + Mi.w*x3.x;
                    ov.y = Mi.x*x0.y + Mi.y*x1.y + Mi.z*x2.y + Mi.w*x3.y;
                    ov.z = Mi.x*x0.z + Mi.y*x1.z + Mi.z*x2.z + Mi.w*x3.z;
                    ov.w = Mi.x*x0.w + Mi.y*x1.w + Mi.z*x2.w + Mi.w*x3.w;
                    __stcs(reinterpret_cast<float4*>(o + i * DDIM), ov);
                }
            }
        }
        // no trailing barrier: next iteration's bar A orders sP/sRaw/sM reuse.
    }
}

extern "C" void kernel_launch(void* const* d_in, const int* in_sizes, int n_in,
                              void* d_out, int out_size)
{
    const float* x  = (const float*)d_in[0];
    const float* Wr = (const float*)d_in[1];
    const float* br = (const float*)d_in[2];
    float* out = (float*)d_out;

    int ntok = in_sizes[0] / (WS * DDIM);   // 8192

    cudaFuncSetAttribute(mchc_kernel,
                         cudaFuncAttributeMaxDynamicSharedMemorySize, SMEM_BYTES);

    int sms = 148, dev = 0;
    if (cudaGetDevice(&dev) == cudaSuccess) {
        int v = 0;
        if (cudaDeviceGetAttribute(&v, cudaDevAttrMultiProcessorCount, dev) == cudaSuccess && v > 0)
            sms = v;
    }
    int ngroups = (ntok + G - 1) / G;
    int grid = (ngroups < sms) ? ngroups : sms;

    mchc_kernel<<<grid, THREADS, SMEM_BYTES>>>(x, Wr, br, out, ntok);
}